// round 1
// baseline (speedup 1.0000x reference)
#include <cuda_runtime.h>

// ---------------------------------------------------------------------------
// second_roi: the whole pipeline is affine in `project`.
//   out[n,o] = sum_k A2[k][o] * project[n][k] + bias[o],  k = c*196 + p*14 + q
// A2 is built by folding w_note/w_reg <- w3 <- w2 <- w1 and the fixed-box
// RoIAlign bilinear map (separable, 2 nnz per row).
// ---------------------------------------------------------------------------

#define NIMG   512
#define CCH    512
#define HWDIM  14
#define HW     196
#define KTOT   (CCH * HW)        // 100352
#define RDIM   490               // 10 outputs * 49 spatial
#define NOUT   10
#define NSLICE 392
#define SLICEK 256               // NSLICE * SLICEK == KTOT

typedef unsigned long long ull;

__device__ __forceinline__ ull fma2(ull a, ull b, ull c) {
    ull d; asm("fma.rn.f32x2 %0, %1, %2, %3;" : "=l"(d) : "l"(a), "l"(b), "l"(c)); return d;
}
__device__ __forceinline__ ull add2(ull a, ull b) {
    ull d; asm("add.rn.f32x2 %0, %1, %2;" : "=l"(d) : "l"(a), "l"(b)); return d;
}
__device__ __forceinline__ ull dup2(float x) {
    ull d; asm("mov.b64 %0, {%1, %1};" : "=l"(d) : "f"(x)); return d;
}
__device__ __forceinline__ void unpk(ull v, float& lo, float& hi) {
    asm("mov.b64 {%0, %1}, %2;" : "=f"(lo), "=f"(hi) : "l"(v));
}

// ------------------------- device scratch (no allocs) -----------------------
__device__ float g_M [RDIM * 512];
__device__ float g_T1[RDIM * 512];
__device__ float g_T2[RDIM * 512];
__device__ float g_T3[RDIM * 512];
__device__ float g_A2[(size_t)KTOT * NOUT];            // ~4 MB, layout [k][o]
__device__ float g_part[(size_t)NSLICE * NIMG * NOUT]; // ~8 MB
__device__ float g_sM[NOUT * 512];
__device__ float g_bias[NOUT];

// --------------------------------------------------------------------------
// Gather M[r][c] = w[o][c*49 + ij],  r = o*49 + ij
// --------------------------------------------------------------------------
__global__ void k_gather(const float* __restrict__ wn, const float* __restrict__ wr) {
    int idx = blockIdx.x * 256 + threadIdx.x;
    if (idx >= RDIM * 512) return;
    int r = idx / 512, c = idx % 512;
    int o = r / 49, ij = r % 49;
    const float* src = (o < 2) ? (wn + (size_t)o * 25088) : (wr + (size_t)(o - 2) * 25088);
    g_M[r * 512 + c] = src[c * 49 + ij];
}

// --------------------------------------------------------------------------
// sM[o][c] = sum_ij w[o][c*49+ij]   (for the bias fold)
// --------------------------------------------------------------------------
__global__ void k_sM(const float* __restrict__ wn, const float* __restrict__ wr) {
    int idx = blockIdx.x * 256 + threadIdx.x;   // < 5120
    int o = idx / 512, c = idx % 512;
    const float* src = (o < 2) ? (wn + (size_t)o * 25088) : (wr + (size_t)(o - 2) * 25088);
    float s = 0.f;
    #pragma unroll
    for (int t = 0; t < 49; t++) s += src[c * 49 + t];
    g_sM[idx] = s;
}

// --------------------------------------------------------------------------
// bias chain: beta2 = W2 b1 + b2; beta3 = W3 beta2 + b3;
// bias[o] = b_head[o] + sum_c sM[o][c] * beta3[c]
// (RoIAlign bilinear weights sum to 1, so a channel-constant bias passes through)
// --------------------------------------------------------------------------
__global__ void k_bias(const float* __restrict__ w2, const float* __restrict__ b1,
                       const float* __restrict__ b2, const float* __restrict__ w3,
                       const float* __restrict__ b3, const float* __restrict__ bn,
                       const float* __restrict__ br) {
    __shared__ float s2[512];
    __shared__ float s3[512];
    int c = threadIdx.x;
    float s = b2[c];
    for (int k = 0; k < 512; k++) s += w2[c * 512 + k] * b1[k];
    s2[c] = s;
    __syncthreads();
    float t = b3[c];
    for (int k = 0; k < 512; k++) t += w3[c * 512 + k] * s2[k];
    s3[c] = t;
    __syncthreads();
    if (c < 320) {
        int o = c >> 5, lane = c & 31;
        float acc = 0.f;
        for (int k = lane; k < 512; k += 32) acc += g_sM[o * 512 + k] * s3[k];
        #pragma unroll
        for (int off = 16; off; off >>= 1) acc += __shfl_xor_sync(0xffffffffu, acc, off);
        if (lane == 0) g_bias[o] = acc + ((o < 2) ? bn[o] : br[o - 2]);
    }
}

// --------------------------------------------------------------------------
// Fold SGEMM: C[RDIMx512] = A[RDIMx512] @ B[512x512]
// stage 0: g_M  @ w3 -> g_T1 ; stage 1: g_T1 @ w2 -> g_T2 ; stage 2: g_T2 @ w1 -> g_T3
// 64x32 tile, 256 threads, 2x4 micro-tile via packed f32x2 FMA.
// --------------------------------------------------------------------------
__global__ void __launch_bounds__(256) k_sgemm(const float* __restrict__ B, int stage) {
    const float* A = (stage == 0) ? g_M : (stage == 1) ? g_T1 : g_T2;
    float*       C = (stage == 0) ? g_T1 : (stage == 1) ? g_T2 : g_T3;

    __shared__ float As[32][66];   // [kk][row], padded
    __shared__ float Bs[32][32];   // [kk][col]

    int row0 = blockIdx.x * 64;
    int col0 = blockIdx.y * 32;
    int tid  = threadIdx.x;
    int rg = tid & 31;     // rows 2*rg, 2*rg+1
    int cg = tid >> 5;     // cols 4*cg .. +3

    ull a00 = 0, a01 = 0, a10 = 0, a11 = 0;

    for (int k0 = 0; k0 < 512; k0 += 32) {
        #pragma unroll
        for (int i = 0; i < 8; i++) {
            int idx = tid + i * 256;
            int kk = idx & 31, row = idx >> 5;
            int gr = row0 + row;
            As[kk][row] = (gr < RDIM) ? A[gr * 512 + k0 + kk] : 0.0f;
        }
        #pragma unroll
        for (int i = 0; i < 4; i++) {
            int idx = tid + i * 256;
            int kk = idx >> 5, col = idx & 31;
            Bs[kk][col] = B[(k0 + kk) * 512 + col0 + col];
        }
        __syncthreads();
        #pragma unroll
        for (int kk = 0; kk < 32; kk++) {
            ull d0  = dup2(As[kk][2 * rg]);
            ull d1  = dup2(As[kk][2 * rg + 1]);
            ull b01 = *reinterpret_cast<const ull*>(&Bs[kk][4 * cg]);
            ull b23 = *reinterpret_cast<const ull*>(&Bs[kk][4 * cg + 2]);
            a00 = fma2(b01, d0, a00);
            a01 = fma2(b23, d0, a01);
            a10 = fma2(b01, d1, a10);
            a11 = fma2(b23, d1, a11);
        }
        __syncthreads();
    }

    int r = row0 + 2 * rg, cc = col0 + 4 * cg;
    float v0, v1, v2, v3;
    if (r < RDIM) {
        unpk(a00, v0, v1); unpk(a01, v2, v3);
        C[r * 512 + cc] = v0; C[r * 512 + cc + 1] = v1;
        C[r * 512 + cc + 2] = v2; C[r * 512 + cc + 3] = v3;
    }
    if (r + 1 < RDIM) {
        unpk(a10, v0, v1); unpk(a11, v2, v3);
        C[(r + 1) * 512 + cc] = v0; C[(r + 1) * 512 + cc + 1] = v1;
        C[(r + 1) * 512 + cc + 2] = v2; C[(r + 1) * 512 + cc + 3] = v3;
    }
}

// --------------------------------------------------------------------------
// Spatial expand: A2[(c*196 + p*14 + q)][o] = sum_{ti,tj} Ry[ti,p]*Rx[tj,q]*T3[(o*49+ti*7+tj)][c]
// Fixed box (0,0,13,13): sample positions ys = xs = 3/7 + t*13/7, bilinear, clipped.
// block = pq (196), thread = c (512) -> coalesced T3 reads.
// --------------------------------------------------------------------------
__global__ void k_spatial() {
    int pq = blockIdx.x;
    int p = pq / 14, q = pq % 14;
    int c = threadIdx.x;

    float wyp[7], wxq[7];
    float sw  = (13.0f - 0.0f) / 7.0f;
    float n0  = (0.0f + sw * 0.5f - 0.5f) / 13.0f;
    float nw  = sw * 6.0f / 13.0f;
    float stp = nw * 13.0f / 6.0f;
    float b0  = n0 * 13.0f;
    #pragma unroll
    for (int t = 0; t < 7; t++) {
        float s = b0 + (float)t * stp;
        float f = floorf(s);
        float w = s - f;
        int i0 = min(max((int)f, 0), 13);
        int i1 = min(i0 + 1, 13);
        float wy = ((i0 == p) ? (1.0f - w) : 0.0f) + ((i1 == p) ? w : 0.0f);
        float wx = ((i0 == q) ? (1.0f - w) : 0.0f) + ((i1 == q) ? w : 0.0f);
        wyp[t] = wy;
        wxq[t] = wx;
    }

    float val[NOUT];
    #pragma unroll
    for (int o = 0; o < NOUT; o++) val[o] = 0.f;

    for (int ti = 0; ti < 7; ti++) {
        if (wyp[ti] == 0.0f) continue;
        for (int tj = 0; tj < 7; tj++) {
            float wgt = wyp[ti] * wxq[tj];
            if (wgt == 0.0f) continue;
            int r = ti * 7 + tj;
            #pragma unroll
            for (int o = 0; o < NOUT; o++)
                val[o] += wgt * g_T3[(o * 49 + r) * 512 + c];
        }
    }

    size_t base = ((size_t)c * 196 + pq) * NOUT;
    #pragma unroll
    for (int o = 0; o < NOUT; o++) g_A2[base + o] = val[o];
}

// --------------------------------------------------------------------------
// Main pass: partial[slice][n][o] = sum_{k in slice} P[n][k] * A2[k][o]
// 392 blocks x 256 thr. A2 slice staged in smem. Warp = 4 n x 8 k-phases:
// P loads fully coalesced (4x128B lines / LDG.128), A reads broadcast 4-wide.
// f32x2 packed FMA over output pairs (acc2[5] per thread).
// --------------------------------------------------------------------------
__global__ void __launch_bounds__(256) k_main(const float* __restrict__ P) {
    __shared__ float sA[SLICEK * NOUT];   // 2560 floats, layout [k_local][o]
    int slice = blockIdx.x;
    size_t k0 = (size_t)slice * SLICEK;

    {
        const float4* src = reinterpret_cast<const float4*>(g_A2 + k0 * NOUT);
        float4* dst = reinterpret_cast<float4*>(sA);
        for (int i = threadIdx.x; i < SLICEK * NOUT / 4; i += 256) dst[i] = src[i];
    }
    __syncthreads();

    int lane = threadIdx.x & 31, w = threadIdx.x >> 5;
    int kp = lane & 7, nl = lane >> 3;

    for (int pass = 0; pass < 16; pass++) {
        int n = pass * 32 + w * 4 + nl;
        const float* prow = P + (size_t)n * KTOT + k0 + kp * 4;
        ull acc[5] = {0ull, 0ull, 0ull, 0ull, 0ull};

        #pragma unroll
        for (int it = 0; it < SLICEK / 32; it++) {
            float4 p4 = *reinterpret_cast<const float4*>(prow + it * 32);
            const ull* a64 = reinterpret_cast<const ull*>(sA + it * 320 + kp * 40);
            ull dk0 = dup2(p4.x), dk1 = dup2(p4.y), dk2 = dup2(p4.z), dk3 = dup2(p4.w);
            #pragma unroll
            for (int t = 0; t < 5; t++) {
                acc[t] = fma2(a64[t],      dk0, acc[t]);
                acc[t] = fma2(a64[5 + t],  dk1, acc[t]);
                acc[t] = fma2(a64[10 + t], dk2, acc[t]);
                acc[t] = fma2(a64[15 + t], dk3, acc[t]);
            }
        }

        // reduce over the 8 k-phase lanes (xor within groups of 8)
        #pragma unroll
        for (int off = 1; off < 8; off <<= 1) {
            #pragma unroll
            for (int t = 0; t < 5; t++)
                acc[t] = add2(acc[t], __shfl_xor_sync(0xffffffffu, acc[t], off));
        }

        if (kp == 0) {
            float* dst = g_part + ((size_t)slice * NIMG + n) * NOUT;
            #pragma unroll
            for (int t = 0; t < 5; t++) {
                float lo, hi; unpk(acc[t], lo, hi);
                dst[2 * t] = lo; dst[2 * t + 1] = hi;
            }
        }
    }
}

// --------------------------------------------------------------------------
// Deterministic reduction of partials + bias; scatter to (note, reg) layout.
// --------------------------------------------------------------------------
__global__ void k_reduce(float* __restrict__ out) {
    int idx = blockIdx.x * 256 + threadIdx.x;   // < 5120
    float s = 0.f;
    #pragma unroll 8
    for (int sl = 0; sl < NSLICE; sl++) s += g_part[(size_t)sl * (NIMG * NOUT) + idx];
    int n = idx / NOUT, o = idx % NOUT;
    s += g_bias[o];
    if (o < 2) out[n * 2 + o] = s;
    else       out[1024 + n * 8 + (o - 2)] = s;
}

// --------------------------------------------------------------------------
extern "C" void kernel_launch(void* const* d_in, const int* in_sizes, int n_in,
                              void* d_out, int out_size) {
    const float* project = (const float*)d_in[0];
    const float* w1 = (const float*)d_in[1];
    const float* b1 = (const float*)d_in[2];
    const float* w2 = (const float*)d_in[3];
    const float* b2 = (const float*)d_in[4];
    const float* w3 = (const float*)d_in[5];
    const float* b3 = (const float*)d_in[6];
    const float* wn = (const float*)d_in[7];
    const float* bn = (const float*)d_in[8];
    const float* wr = (const float*)d_in[9];
    const float* br = (const float*)d_in[10];
    float* out = (float*)d_out;

    k_gather<<<(RDIM * 512 + 255) / 256, 256>>>(wn, wr);
    k_sM<<<20, 256>>>(wn, wr);
    k_bias<<<1, 512>>>(w2, b1, b2, w3, b3, bn, br);

    dim3 gg(8, 16);
    k_sgemm<<<gg, 256>>>(w3, 0);   // g_M  @ w3 -> g_T1
    k_sgemm<<<gg, 256>>>(w2, 1);   // g_T1 @ w2 -> g_T2
    k_sgemm<<<gg, 256>>>(w1, 2);   // g_T2 @ w1 -> g_T3

    k_spatial<<<HW, 512>>>();

    k_main<<<NSLICE, 256>>>(project);
    k_reduce<<<20, 256>>>(out);
}

// round 2
// speedup vs baseline: 2.8817x; 2.8817x over previous
#include <cuda_runtime.h>

// ---------------------------------------------------------------------------
// second_roi: pipeline is affine in `project`, and RoIAlign (fixed box) commutes
// with 1x1 convs. Two passes over data:
//   Pass1 (input-only): Pr[n, r, c] = sum_s R[r,s] * P[n,c,s]   (205MB -> 51MB)
//          fused with U = w2@w1, V = M@w3, bias chain (all independent)
//   GfP: Gf = V @ U (split-K=4 partials)
//   Pass2: out[n,o] = sum_{r,c} Pr[n,r,c] * Gf[o*49+r, c] + bias[o]
// ---------------------------------------------------------------------------

#define NIMG   512
#define CCH    512
#define HW     196
#define R49    49
#define KP     25088          // 49*512, per-image reduced feature count
#define NOUT   10
#define NSLICE 98             // (r, c-half) slices of 256 for pass2
#define GFSTRIDE 250880       // 490*512

typedef unsigned long long ull;

__device__ __forceinline__ ull fma2(ull a, ull b, ull c) {
    ull d; asm("fma.rn.f32x2 %0, %1, %2, %3;" : "=l"(d) : "l"(a), "l"(b), "l"(c)); return d;
}
__device__ __forceinline__ ull add2(ull a, ull b) {
    ull d; asm("add.rn.f32x2 %0, %1, %2;" : "=l"(d) : "l"(a), "l"(b)); return d;
}
__device__ __forceinline__ ull dup2(float x) {
    ull d; asm("mov.b64 %0, {%1, %1};" : "=l"(d) : "f"(x)); return d;
}
__device__ __forceinline__ void unpk(ull v, float& lo, float& hi) {
    asm("mov.b64 {%0, %1}, %2;" : "=f"(lo), "=f"(hi) : "l"(v));
}

// ------------------------- device scratch (no allocs) -----------------------
__device__ float g_M  [490 * 512];
__device__ float g_U  [512 * 512];
__device__ float g_V  [490 * 512];
__device__ float g_GfP[4 * GFSTRIDE];
__device__ float g_Pr [(size_t)NIMG * KP];             // 51.4 MB
__device__ float g_part[(size_t)NSLICE * NIMG * NOUT]; // 2 MB
__device__ float g_sM [NOUT * 512];
__device__ float g_bias[NOUT];

// ============================================================================
// K0: gather M + sM   (input-only, tiny)
// ============================================================================
__global__ void __launch_bounds__(256) k_pre(const float* __restrict__ wn,
                                             const float* __restrict__ wr) {
    int b = blockIdx.x;
    if (b < 980) {
        int idx = b * 256 + threadIdx.x;
        if (idx < 490 * 512) {
            int r = idx >> 9, c = idx & 511;
            int o = r / 49, ij = r % 49;
            const float* src = (o < 2) ? (wn + (size_t)o * 25088)
                                       : (wr + (size_t)(o - 2) * 25088);
            g_M[idx] = src[c * 49 + ij];
        }
    } else {
        int idx = (b - 980) * 256 + threadIdx.x;   // < 5120
        int o = idx >> 9, c = idx & 511;
        const float* src = (o < 2) ? (wn + (size_t)o * 25088)
                                   : (wr + (size_t)(o - 2) * 25088);
        float s = 0.f;
        #pragma unroll
        for (int t = 0; t < 49; t++) s += src[c * 49 + t];
        g_sM[idx] = s;
    }
}

// ============================================================================
// device SGEMM tile: C[64x32] += A[rows x 512] @ B[512 x 512] over k in [kbeg,kend)
// 256 threads, 2x4 micro via f32x2.
// ============================================================================
__device__ __forceinline__ void sgemm_tile(const float* __restrict__ A,
                                           const float* __restrict__ B,
                                           float* __restrict__ C,
                                           int nrows, int row0, int col0,
                                           int kbeg, int kend, float* sh) {
    float* As = sh;               // 32*66
    float* Bs = sh + 32 * 66;     // 32*32
    int tid = threadIdx.x;
    int rg = tid & 31, cg = tid >> 5;
    ull a00 = 0, a01 = 0, a10 = 0, a11 = 0;

    for (int k0 = kbeg; k0 < kend; k0 += 32) {
        #pragma unroll
        for (int i = 0; i < 8; i++) {
            int idx = tid + i * 256;
            int kk = idx & 31, row = idx >> 5;
            int gr = row0 + row;
            As[kk * 66 + row] = (gr < nrows) ? A[gr * 512 + k0 + kk] : 0.0f;
        }
        #pragma unroll
        for (int i = 0; i < 4; i++) {
            int idx = tid + i * 256;
            int kk = idx >> 5, col = idx & 31;
            Bs[kk * 32 + col] = B[(k0 + kk) * 512 + col0 + col];
        }
        __syncthreads();
        #pragma unroll
        for (int kk = 0; kk < 32; kk++) {
            ull d0  = dup2(As[kk * 66 + 2 * rg]);
            ull d1  = dup2(As[kk * 66 + 2 * rg + 1]);
            ull b01 = *reinterpret_cast<const ull*>(&Bs[kk * 32 + 4 * cg]);
            ull b23 = *reinterpret_cast<const ull*>(&Bs[kk * 32 + 4 * cg + 2]);
            a00 = fma2(b01, d0, a00);
            a01 = fma2(b23, d0, a01);
            a10 = fma2(b01, d1, a10);
            a11 = fma2(b23, d1, a11);
        }
        __syncthreads();
    }

    int r = row0 + 2 * rg, cc = col0 + 4 * cg;
    float v0, v1, v2, v3;
    if (r < nrows) {
        unpk(a00, v0, v1); unpk(a01, v2, v3);
        C[r * 512 + cc] = v0; C[r * 512 + cc + 1] = v1;
        C[r * 512 + cc + 2] = v2; C[r * 512 + cc + 3] = v3;
    }
    if (r + 1 < nrows) {
        unpk(a10, v0, v1); unpk(a11, v2, v3);
        C[(r + 1) * 512 + cc] = v0; C[(r + 1) * 512 + cc + 1] = v1;
        C[(r + 1) * 512 + cc + 2] = v2; C[(r + 1) * 512 + cc + 3] = v3;
    }
}

// ============================================================================
// device: bias chain (one block, 256 threads). beta2 = w2 b1 + b2,
// beta3 = w3 beta2 + b3, bias[o] = head_b[o] + sum_c sM[o,c] beta3[c]
// ============================================================================
__device__ void bias_block(const float* __restrict__ w2, const float* __restrict__ b1,
                           const float* __restrict__ b2, const float* __restrict__ w3,
                           const float* __restrict__ b3, const float* __restrict__ bn,
                           const float* __restrict__ br, float* sh) {
    float* sv = sh;         // 512: current input vector
    float* so = sh + 512;   // 512: output vector
    int t = threadIdx.x;
    sv[t] = b1[t]; sv[t + 256] = b1[t + 256];
    __syncthreads();
    // beta2
    #pragma unroll
    for (int rep = 0; rep < 2; rep++) {
        int c = t + rep * 256;
        const float4* row = reinterpret_cast<const float4*>(w2 + (size_t)c * 512);
        const float4* bv  = reinterpret_cast<const float4*>(sv);
        float a0 = 0, a1 = 0, a2 = 0, a3 = 0;
        #pragma unroll 4
        for (int k = 0; k < 128; k++) {
            float4 v = row[k]; float4 u = bv[k];
            a0 += v.x * u.x; a1 += v.y * u.y; a2 += v.z * u.z; a3 += v.w * u.w;
        }
        so[c] = b2[c] + ((a0 + a1) + (a2 + a3));
    }
    __syncthreads();
    sv[t] = so[t]; sv[t + 256] = so[t + 256];
    __syncthreads();
    // beta3
    #pragma unroll
    for (int rep = 0; rep < 2; rep++) {
        int c = t + rep * 256;
        const float4* row = reinterpret_cast<const float4*>(w3 + (size_t)c * 512);
        const float4* bv  = reinterpret_cast<const float4*>(sv);
        float a0 = 0, a1 = 0, a2 = 0, a3 = 0;
        #pragma unroll 4
        for (int k = 0; k < 128; k++) {
            float4 v = row[k]; float4 u = bv[k];
            a0 += v.x * u.x; a1 += v.y * u.y; a2 += v.z * u.z; a3 += v.w * u.w;
        }
        so[c] = b3[c] + ((a0 + a1) + (a2 + a3));
    }
    __syncthreads();
    int w = t >> 5, lane = t & 31;
    for (int o = w; o < NOUT; o += 8) {
        float acc = 0.f;
        for (int k = lane; k < 512; k += 32) acc += g_sM[o * 512 + k] * so[k];
        #pragma unroll
        for (int off = 16; off; off >>= 1) acc += __shfl_xor_sync(0xffffffffu, acc, off);
        if (lane == 0) g_bias[o] = acc + ((o < 2) ? bn[o] : br[o - 2]);
    }
}

// ============================================================================
// device: spatial reduce block. bidx in [0, 8192): n = bidx>>4, c0 = (bidx&15)*32.
// Pr[n][r*512 + c] = bilinear-sample-sum over P[n][c][.][.]
// ============================================================================
__device__ void spatial_block(const float* __restrict__ P, int bidx, float* sh) {
    int n  = bidx >> 4;
    int c0 = (bidx & 15) * 32;
    const float* src = P + ((size_t)n * 512 + c0) * 196;
    int tid = threadIdx.x;

    // load 32 channels x 196 into smem, rows padded to 197 (conflict-free reads)
    for (int i4 = tid; i4 < 32 * 49; i4 += 256) {
        int c = i4 / 49, j = i4 % 49;
        float4 v = *reinterpret_cast<const float4*>(src + c * 196 + j * 4);
        float* d = sh + c * 197 + j * 4;
        d[0] = v.x; d[1] = v.y; d[2] = v.z; d[3] = v.w;
    }
    __syncthreads();

    // sample-position constants, fp32 path identical to reference
    float swf = 13.0f / 7.0f;
    float n0  = (swf * 0.5f - 0.5f) / 13.0f;
    float nw  = swf * 6.0f / 13.0f;
    float b0  = n0 * 13.0f;
    float stp = nw * 13.0f / 6.0f;

    for (int idx = tid; idx < 49 * 32; idx += 256) {
        int r = idx >> 5, c = idx & 31;
        int ti = r / 7, tj = r % 7;
        float py = b0 + (float)ti * stp;
        float px = b0 + (float)tj * stp;
        float fy = floorf(py), fx = floorf(px);
        float wy = py - fy,    wx = px - fx;
        int y0 = min(max((int)fy, 0), 13); int y1 = min(y0 + 1, 13);
        int x0 = min(max((int)fx, 0), 13); int x1 = min(x0 + 1, 13);
        const float* row = sh + c * 197;
        float v00 = row[y0 * 14 + x0], v01 = row[y0 * 14 + x1];
        float v10 = row[y1 * 14 + x0], v11 = row[y1 * 14 + x1];
        float top = v00 + (v01 - v00) * wx;
        float bot = v10 + (v11 - v10) * wx;
        g_Pr[(size_t)n * KP + r * 512 + c0 + c] = top + (bot - top) * wy;
    }
}

// ============================================================================
// K_A fused: [bias(1)] [U=w2@w1 (128)] [V=M@w3 (128)] [Pr reduce (8192)]
// ============================================================================
__global__ void __launch_bounds__(256) k_fused(const float* __restrict__ P,
        const float* __restrict__ w1, const float* __restrict__ b1,
        const float* __restrict__ w2, const float* __restrict__ b2,
        const float* __restrict__ w3, const float* __restrict__ b3,
        const float* __restrict__ bn, const float* __restrict__ br) {
    __shared__ float sh[32 * 197];   // 25.2 KB, reused by all roles
    int b = blockIdx.x;
    if (b == 0) {
        bias_block(w2, b1, b2, w3, b3, bn, br, sh);
    } else if (b < 129) {
        int t = b - 1;
        sgemm_tile(w2, w1, g_U, 512, (t & 7) * 64, (t >> 3) * 32, 0, 512, sh);
    } else if (b < 257) {
        int t = b - 129;
        sgemm_tile(g_M, w3, g_V, 490, (t & 7) * 64, (t >> 3) * 32, 0, 512, sh);
    } else {
        spatial_block(P, b - 257, sh);
    }
}

// ============================================================================
// K_B: Gf = V @ U, split-K=4 into g_GfP partials. 512 blocks.
// ============================================================================
__global__ void __launch_bounds__(256) k_gf() {
    __shared__ float sh[32 * 66 + 32 * 32];
    int bx = blockIdx.x;
    int kp = bx & 3, rc = bx >> 2;
    int row0 = (rc & 7) * 64, col0 = (rc >> 3) * 32;
    sgemm_tile(g_V, g_U, g_GfP + (size_t)kp * GFSTRIDE, 490, row0, col0,
               kp * 128, kp * 128 + 128, sh);
}

// ============================================================================
// K_C: partial[s][n][o] = sum_{cl} Pr[n][r*512+c0+cl] * Gf[o*49+r][c0+cl]
// grid 392 = 98 slices x 4 n-quarters. Warp = 4n x 8 k-lanes, f32x2 accs.
// ============================================================================
__global__ void __launch_bounds__(256) k_pass2() {
    __shared__ float sA[256 * NOUT];   // [cl][o]
    int s  = blockIdx.x >> 2, nq = blockIdx.x & 3;
    int r  = s >> 1;
    int c0 = (s & 1) * 256;

    for (int t = threadIdx.x; t < 2560; t += 256) {
        int o = t >> 8, cl = t & 255;
        size_t base = ((size_t)(o * 49 + r)) * 512 + c0 + cl;
        float v = g_GfP[base] + g_GfP[GFSTRIDE + base]
                + g_GfP[2 * (size_t)GFSTRIDE + base] + g_GfP[3 * (size_t)GFSTRIDE + base];
        sA[cl * NOUT + o] = v;
    }
    __syncthreads();

    int lane = threadIdx.x & 31, w = threadIdx.x >> 5;
    int kp = lane & 7, nl = lane >> 3;

    for (int pass = 0; pass < 4; pass++) {
        int n = nq * 128 + pass * 32 + w * 4 + nl;
        const float* prow = g_Pr + (size_t)n * KP + r * 512 + c0 + kp * 4;
        ull acc[5] = {0ull, 0ull, 0ull, 0ull, 0ull};

        #pragma unroll
        for (int it = 0; it < 8; it++) {
            float4 p4 = *reinterpret_cast<const float4*>(prow + it * 32);
            const ull* a64 = reinterpret_cast<const ull*>(sA + it * 320 + kp * 40);
            ull dk0 = dup2(p4.x), dk1 = dup2(p4.y), dk2 = dup2(p4.z), dk3 = dup2(p4.w);
            #pragma unroll
            for (int t = 0; t < 5; t++) {
                acc[t] = fma2(a64[t],      dk0, acc[t]);
                acc[t] = fma2(a64[5 + t],  dk1, acc[t]);
                acc[t] = fma2(a64[10 + t], dk2, acc[t]);
                acc[t] = fma2(a64[15 + t], dk3, acc[t]);
            }
        }

        #pragma unroll
        for (int off = 1; off < 8; off <<= 1) {
            #pragma unroll
            for (int t = 0; t < 5; t++)
                acc[t] = add2(acc[t], __shfl_xor_sync(0xffffffffu, acc[t], off));
        }

        if (kp == 0) {
            float* dst = g_part + ((size_t)s * NIMG + n) * NOUT;
            #pragma unroll
            for (int t = 0; t < 5; t++) {
                float lo, hi; unpk(acc[t], lo, hi);
                dst[2 * t] = lo; dst[2 * t + 1] = hi;
            }
        }
    }
}

// ============================================================================
// K_D: deterministic reduce over 98 slices + bias + scatter to (note, reg)
// ============================================================================
__global__ void __launch_bounds__(256) k_reduce(float* __restrict__ out) {
    int idx = blockIdx.x * 256 + threadIdx.x;   // < 5120
    float s = 0.f;
    #pragma unroll 7
    for (int sl = 0; sl < NSLICE; sl++) s += g_part[(size_t)sl * (NIMG * NOUT) + idx];
    int n = idx / NOUT, o = idx % NOUT;
    s += g_bias[o];
    if (o < 2) out[n * 2 + o] = s;
    else       out[1024 + n * 8 + (o - 2)] = s;
}

// ---------------------------------------------------------------------------
extern "C" void kernel_launch(void* const* d_in, const int* in_sizes, int n_in,
                              void* d_out, int out_size) {
    const float* project = (const float*)d_in[0];
    const float* w1 = (const float*)d_in[1];
    const float* b1 = (const float*)d_in[2];
    const float* w2 = (const float*)d_in[3];
    const float* b2 = (const float*)d_in[4];
    const float* w3 = (const float*)d_in[5];
    const float* b3 = (const float*)d_in[6];
    const float* wn = (const float*)d_in[7];
    const float* bn = (const float*)d_in[8];
    const float* wr = (const float*)d_in[9];
    const float* br = (const float*)d_in[10];
    float* out = (float*)d_out;

    k_pre  <<<1000, 256>>>(wn, wr);
    k_fused<<<8449, 256>>>(project, w1, b1, w2, b2, w3, b3, bn, br);
    k_gf   <<<512,  256>>>();
    k_pass2<<<392,  256>>>();
    k_reduce<<<20,  256>>>(out);
}